// round 9
// baseline (speedup 1.0000x reference)
#include <cuda_runtime.h>
#include <cuda_fp16.h>
#include <math.h>

// ---------------------------------------------------------------------------
// 2-layer LSTM, H=1024, T=4096 sequential steps. Persistent kernel, 146 CTAs.
//   A (0..51):   layer-0. W_hh0 fully in REGISTERS. G0 prefetch in regs.
//   B (52..145): layer-1. W_ih1 in SMEM (consumed pre-poll), W_hh1 in
//                REGISTERS (post-poll phase is pure reg HFMA2).
// ROUND-9: all-warps polling, lane-direct h loads (no smem staging, one
//   syncthreads/step), parity-double-buffered gate exchange, reg-resident
//   cell state + biases. Monotonic h history + banked release counters.
// ---------------------------------------------------------------------------

#define H        1024
#define T_STEPS  4096
#define GATES    4096
#define NA       52          // layer-0 CTAs
#define NUA      20          // units per A CTA (last ragged: 4)
#define NB       94          // layer-1 CTAs
#define NUB      11          // units per B CTA (last ragged: 1)
#define GRID     (NA + NB)   // 146
#define THREADS  512
#define BASE_OUT ((size_t)T_STEPS * H)
#define NBANKS   8

#define A_NROWS  (NUA * 4)   // 80
#define B_NROWS  (NUB * 4)   // 44

// ---- shared memory: B = [W_ih1 | sg parity]; A = [sg parity] ----
#define B_W_BYTES (B_NROWS * H * 2)            // 90112
#define B_SG_OFF  (B_W_BYTES)                  // 2 x 44 floats
#define SMEM_BYTES (B_SG_OFF + 2 * B_NROWS * 4 + 64)

// ---- device-global scratch ----
__device__ float          g_G0[(size_t)T_STEPS * GATES];        // 64 MB
__device__ unsigned short g_Hh0[(size_t)(T_STEPS + 1) * H];     // h0 history fp16
__device__ unsigned short g_Hh1[(size_t)(T_STEPS + 1) * H];     // h1 history fp16
__device__ unsigned       g_cntA_b[NBANKS * 64];
__device__ unsigned       g_cntB_b[NBANKS * 64];

__device__ __forceinline__ unsigned ld_acquire(const unsigned* p) {
    unsigned v;
    asm volatile("ld.acquire.gpu.global.u32 %0, [%1];"
                 : "=r"(v) : "l"(p) : "memory");
    return v;
}
__device__ __forceinline__ void red_release_add1(unsigned* p) {
    asm volatile("red.release.gpu.global.add.u32 [%0], %1;"
                 :: "l"(p), "r"(1u) : "memory");
}
__device__ __forceinline__ void stcg_u16(unsigned short* p, unsigned short v) {
    asm volatile("st.global.cg.u16 [%0], %1;" :: "l"(p), "h"(v));
}
__device__ __forceinline__ uint4 ldcg_u128(const uint4* p) {
    uint4 v;
    asm volatile("ld.global.cg.v4.u32 {%0,%1,%2,%3}, [%4];"
                 : "=r"(v.x), "=r"(v.y), "=r"(v.z), "=r"(v.w) : "l"(p));
    return v;
}

// full-warp poll: sum of 8 banks >= target
__device__ __forceinline__ void wait_banks(const unsigned* banks,
                                           unsigned target) {
    const int lane = threadIdx.x & 31;
    for (;;) {
        unsigned v = (lane < NBANKS) ? ld_acquire(&banks[lane << 6]) : 0u;
        v += __shfl_xor_sync(0xffffffffu, v, 1);
        v += __shfl_xor_sync(0xffffffffu, v, 2);
        v += __shfl_xor_sync(0xffffffffu, v, 4);
        v  = __shfl_sync(0xffffffffu, v, 0);
        if (v >= target) return;
    }
}

__device__ __forceinline__ void mac_granule4(const uint4& wq, const uint4& hq,
                                             __half2* acc) {
    acc[0] = __hfma2(*(const __half2*)&wq.x, *(const __half2*)&hq.x, acc[0]);
    acc[1] = __hfma2(*(const __half2*)&wq.y, *(const __half2*)&hq.y, acc[1]);
    acc[2] = __hfma2(*(const __half2*)&wq.z, *(const __half2*)&hq.z, acc[2]);
    acc[3] = __hfma2(*(const __half2*)&wq.w, *(const __half2*)&hq.w, acc[3]);
}
__device__ __forceinline__ float acc4_reduce(__half2* acc) {
    acc[0] = __hadd2(acc[0], acc[2]);
    acc[1] = __hadd2(acc[1], acc[3]);
    acc[0] = __hadd2(acc[0], acc[1]);
    float2 f = __half22float2(acc[0]);
    return f.x + f.y;
}
__device__ __forceinline__ float acc8_reduce(__half2* acc) {
    acc[0] = __hadd2(acc[0], acc[4]);
    acc[1] = __hadd2(acc[1], acc[5]);
    acc[2] = __hadd2(acc[2], acc[6]);
    acc[3] = __hadd2(acc[3], acc[7]);
    acc[0] = __hadd2(acc[0], acc[2]);
    acc[1] = __hadd2(acc[1], acc[3]);
    acc[0] = __hadd2(acc[0], acc[1]);
    float2 f = __half22float2(acc[0]);
    return f.x + f.y;
}

__device__ __forceinline__ float fsig(float x) {
    return __fdividef(1.f, 1.f + __expf(-x));
}
__device__ __forceinline__ float ftanh(float x) {
    return 1.f - __fdividef(2.f, __expf(2.f * x) + 1.f);
}
__device__ __forceinline__ unsigned pack_h2(float a, float b) {
    __half2 h = __halves2half2(__float2half_rn(a), __float2half_rn(b));
    return *(unsigned*)&h;
}

// ---------------------------------------------------------------------------
__global__ void init_kernel(const float* __restrict__ hidden) {
    int u = threadIdx.x;
    if (u < H) {
        g_Hh0[u] = __half_as_ushort(__float2half_rn(hidden[u]));
        g_Hh1[u] = __half_as_ushort(__float2half_rn(hidden[H + u]));
    }
    if (u < NBANKS * 64) { g_cntA_b[u] = 0u; g_cntB_b[u] = 0u; }
}

// ---------------------------------------------------------------------------
__global__ void g0_kernel(const float* __restrict__ x,
                          const int*   __restrict__ ip,
                          const int*   __restrict__ port,
                          const float* __restrict__ ip_emb,
                          const float* __restrict__ port_emb,
                          const float* __restrict__ Wih0,
                          const float* __restrict__ bih0,
                          const float* __restrict__ bhh0) {
    __shared__ float sxin[8][33];
    const int t0  = blockIdx.x * 8;
    const int tid = threadIdx.x;

    for (int idx = tid; idx < 8 * 33; idx += 256) {
        int tt = idx / 33, k = idx - tt * 33;
        int t = t0 + tt;
        float v;
        if (k < 17)      v = x[t * 17 + k];
        else if (k < 25) v = ip_emb[ip[t * 8 + (k - 17)]];
        else {
            int s = (k - 25) >> 2, e = (k - 25) & 3;
            v = port_emb[port[t * 2 + s] * 4 + e];
        }
        sxin[tt][k] = v;
    }
    __syncthreads();

    for (int j = tid; j < GATES; j += 256) {
        float w[33];
#pragma unroll
        for (int k = 0; k < 33; ++k) w[k] = __ldg(&Wih0[j * 33 + k]);
        float bias = __ldg(&bih0[j]) + __ldg(&bhh0[j]);
#pragma unroll
        for (int tt = 0; tt < 8; ++tt) {
            float acc = bias;
#pragma unroll
            for (int k = 0; k < 33; ++k) acc = fmaf(w[k], sxin[tt][k], acc);
            g_G0[(size_t)(t0 + tt) * GATES + j] = acc;
        }
    }
}

// ---------------------------------------------------------------------------
__global__ __launch_bounds__(THREADS, 1)
void lstm_kernel(const float* __restrict__ Whh0,
                 const float* __restrict__ Wih1,
                 const float* __restrict__ Whh1,
                 const float* __restrict__ bih1,
                 const float* __restrict__ bhh1,
                 const float* __restrict__ cell,
                 float* __restrict__ out,
                 int write_state) {
    extern __shared__ char smem[];
    const int tid  = threadIdx.x;
    const int lane = tid & 31;
    const int warp = tid >> 5;
    const int cta  = blockIdx.x;

    if (cta < NA) {
        // ================ layer 0 : everything in registers ================
        const int u0 = cta * NUA;
        const int nu = min(NUA, H - u0);
        const int nrows = 4 * nu;
        float* sg = (float*)smem;              // [2][A_NROWS]

        int grow_i[5];
        uint4 w[5][4];
#pragma unroll
        for (int i = 0; i < 5; ++i) {
            int r = warp + 16 * i;
            grow_i[i] = 0;
#pragma unroll
            for (int g = 0; g < 4; ++g) w[i][g] = make_uint4(0u, 0u, 0u, 0u);
            if (r < nrows) {
                int grow = (r & 3) * H + u0 + (r >> 2);
                grow_i[i] = grow;
                const float* src = Whh0 + (size_t)grow * H;
#pragma unroll
                for (int g = 0; g < 4; ++g) {
                    int base = (g * 32 + lane) * 8;
                    float4 f0 = *(const float4*)(src + base);
                    float4 f1 = *(const float4*)(src + base + 4);
                    w[i][g] = make_uint4(pack_h2(f0.x, f0.y), pack_h2(f0.z, f0.w),
                                         pack_h2(f1.x, f1.y), pack_h2(f1.z, f1.w));
                }
            }
        }
        float creg = (warp == 0 && lane < nu) ? cell[u0 + lane] : 0.f;
        __syncthreads();

        for (int t = 0; t < T_STEPS; ++t) {
            // G0 prefetch into regs — in flight during the poll
            float g0v[5];
#pragma unroll
            for (int i = 0; i < 5; ++i) {
                int r = warp + 16 * i;
                g0v[i] = (r < nrows)
                       ? __ldg(&g_G0[(size_t)t * GATES + grow_i[i]]) : 0.f;
            }
            wait_banks(g_cntA_b, (unsigned)(NA * t));     // all warps

            const uint4* hsrc = (const uint4*)(g_Hh0 + (size_t)t * H);
            uint4 hq[4];
#pragma unroll
            for (int g = 0; g < 4; ++g) hq[g] = ldcg_u128(&hsrc[g * 32 + lane]);

            float* sgp = sg + (t & 1) * A_NROWS;
#pragma unroll
            for (int i = 0; i < 5; ++i) {
                int r = warp + 16 * i;
                if (r < nrows) {
                    __half2 acc[4];
#pragma unroll
                    for (int a = 0; a < 4; ++a) acc[a] = __float2half2_rn(0.f);
#pragma unroll
                    for (int g = 0; g < 4; ++g) mac_granule4(w[i][g], hq[g], acc);
                    float s = acc4_reduce(acc);
#pragma unroll
                    for (int o = 16; o > 0; o >>= 1)
                        s += __shfl_xor_sync(0xffffffffu, s, o);
                    if (lane == 0) sgp[r] = s + g0v[i];
                }
            }
            __syncthreads();

            if (warp == 0) {
                if (lane < nu) {
                    float ii = fsig(sgp[lane * 4 + 0]);
                    float ff = fsig(sgp[lane * 4 + 1]);
                    float gg = ftanh(sgp[lane * 4 + 2]);
                    float oo = fsig(sgp[lane * 4 + 3]);
                    float c  = ff * creg + ii * gg;
                    creg = c;
                    float h  = oo * ftanh(c);
                    stcg_u16(&g_Hh0[(size_t)(t + 1) * H + u0 + lane],
                             __half_as_ushort(__float2half_rn(h)));
                    if (t == T_STEPS - 1 && write_state) {
                        out[BASE_OUT + u0 + lane]         = h;   // hf layer 0
                        out[BASE_OUT + 2 * H + u0 + lane] = c;   // cf layer 0
                    }
                }
                __syncwarp();
                if (lane == 0)
                    red_release_add1(&g_cntA_b[(cta & (NBANKS - 1)) << 6]);
            }
        }
    } else {
        // ====== layer 1 : W_ih1 in SMEM (pre-poll), W_hh1 in registers ======
        const int b  = cta - NA;
        const int u0 = b * NUB;
        const int nu = min(NUB, H - u0);
        const int nrows = 4 * nu;
        __half* sw = (__half*)smem;            // W_ih1: nrows x 1024 halves
        float*  sg = (float*)(smem + B_SG_OFF);// [2][B_NROWS]

        for (int idx = tid; idx < nrows * H; idx += THREADS) {
            int r = idx >> 10, k = idx & (H - 1);
            int grow = (r & 3) * H + u0 + (r >> 2);
            sw[idx] = __float2half_rn(Wih1[(size_t)grow * H + k]);
        }
        uint4 w2[3][4];
        float bs[3];
#pragma unroll
        for (int i = 0; i < 3; ++i) {
            int r = warp + 16 * i;
            bs[i] = 0.f;
#pragma unroll
            for (int g = 0; g < 4; ++g) w2[i][g] = make_uint4(0u, 0u, 0u, 0u);
            if (r < nrows) {
                int grow = (r & 3) * H + u0 + (r >> 2);
                bs[i] = __ldg(&bih1[grow]) + __ldg(&bhh1[grow]);
                const float* src = Whh1 + (size_t)grow * H;
#pragma unroll
                for (int g = 0; g < 4; ++g) {
                    int base = (g * 32 + lane) * 8;
                    float4 f0 = *(const float4*)(src + base);
                    float4 f1 = *(const float4*)(src + base + 4);
                    w2[i][g] = make_uint4(pack_h2(f0.x, f0.y), pack_h2(f0.z, f0.w),
                                          pack_h2(f1.x, f1.y), pack_h2(f1.z, f1.w));
                }
            }
        }
        float creg = (warp == 0 && lane < nu) ? cell[H + u0 + lane] : 0.f;
        __syncthreads();

        for (int t = 0; t < T_STEPS; ++t) {
            // ---- phase 1: W_ih1 (SMEM) @ h0(t) — cntA usually far ahead ----
            wait_banks(g_cntA_b, (unsigned)(NA * (t + 1)));
            const uint4* h0src = (const uint4*)(g_Hh0 + (size_t)(t + 1) * H);
            uint4 hq[4];
#pragma unroll
            for (int g = 0; g < 4; ++g) hq[g] = ldcg_u128(&h0src[g * 32 + lane]);

            __half2 acc[3][8];
#pragma unroll
            for (int i = 0; i < 3; ++i)
#pragma unroll
                for (int q = 0; q < 8; ++q) acc[i][q] = __float2half2_rn(0.f);

#pragma unroll
            for (int i = 0; i < 3; ++i) {
                int r = warp + 16 * i;
                if (r < nrows) {
                    const uint4* wrow = (const uint4*)(sw + (size_t)r * H);
#pragma unroll
                    for (int g = 0; g < 4; ++g)
                        mac_granule4(wrow[g * 32 + lane], hq[g], acc[i]);
                }
            }

            // ---- phase 2: W_hh1 (REGS) @ h1(t-1) ----
            wait_banks(g_cntB_b, (unsigned)(NB * t));
            const uint4* h1src = (const uint4*)(g_Hh1 + (size_t)t * H);
#pragma unroll
            for (int g = 0; g < 4; ++g) hq[g] = ldcg_u128(&h1src[g * 32 + lane]);

            float* sgp = sg + (t & 1) * B_NROWS;
#pragma unroll
            for (int i = 0; i < 3; ++i) {
                int r = warp + 16 * i;
                if (r < nrows) {
#pragma unroll
                    for (int g = 0; g < 4; ++g)
                        mac_granule4(w2[i][g], hq[g], acc[i] + 4);
                    float s = acc8_reduce(acc[i]);
#pragma unroll
                    for (int o = 16; o > 0; o >>= 1)
                        s += __shfl_xor_sync(0xffffffffu, s, o);
                    if (lane == 0) sgp[r] = s + bs[i];
                }
            }
            __syncthreads();

            if (warp == 0) {
                if (lane < nu) {
                    float ii = fsig(sgp[lane * 4 + 0]);
                    float ff = fsig(sgp[lane * 4 + 1]);
                    float gg = ftanh(sgp[lane * 4 + 2]);
                    float oo = fsig(sgp[lane * 4 + 3]);
                    float c  = ff * creg + ii * gg;
                    creg = c;
                    float h  = oo * ftanh(c);
                    stcg_u16(&g_Hh1[(size_t)(t + 1) * H + u0 + lane],
                             __half_as_ushort(__float2half_rn(h)));
                    out[(size_t)t * H + u0 + lane] = fmaxf(h, 0.f);
                    if (t == T_STEPS - 1 && write_state) {
                        out[BASE_OUT + H + u0 + lane]     = h;   // hf layer 1
                        out[BASE_OUT + 3 * H + u0 + lane] = c;   // cf layer 1
                    }
                }
                __syncwarp();
                if (lane == 0)
                    red_release_add1(&g_cntB_b[(cta & (NBANKS - 1)) << 6]);
            }
        }
    }
}

// ---------------------------------------------------------------------------
extern "C" void kernel_launch(void* const* d_in, const int* in_sizes, int n_in,
                              void* d_out, int out_size) {
    const float *x = 0, *hidden = 0, *cell = 0, *ip_emb = 0, *port_emb = 0;
    const float *Wih0 = 0, *Whh0 = 0, *bih0 = 0, *bhh0 = 0;
    const float *Wih1 = 0, *Whh1 = 0, *bih1 = 0, *bhh1 = 0;
    const int *ip = 0, *port = 0;

    const float* big[3]  = {0, 0, 0};    int nbig  = 0;
    const float* bias[4] = {0, 0, 0, 0}; int nbias = 0;
    const float* st2[2]  = {0, 0};       int nst2  = 0;

    for (int i = 0; i < n_in; ++i) {
        switch (in_sizes[i]) {
            case 69632:   x        = (const float*)d_in[i]; break;
            case 32768:   ip       = (const int*)  d_in[i]; break;
            case 8192:    port     = (const int*)  d_in[i]; break;
            case 256:     ip_emb   = (const float*)d_in[i]; break;
            case 280000:  port_emb = (const float*)d_in[i]; break;
            case 135168:  Wih0     = (const float*)d_in[i]; break;
            case 4194304: if (nbig  < 3) big[nbig++]   = (const float*)d_in[i]; break;
            case 4096:    if (nbias < 4) bias[nbias++] = (const float*)d_in[i]; break;
            case 2048:    if (nst2  < 2) st2[nst2++]   = (const float*)d_in[i]; break;
            default: break;
        }
    }
    if (nbig == 3 && nbias == 4 && nst2 == 2 && x && ip && port &&
        ip_emb && port_emb && Wih0) {
        Whh0 = big[0]; Wih1 = big[1]; Whh1 = big[2];
        bih0 = bias[0]; bhh0 = bias[1]; bih1 = bias[2]; bhh1 = bias[3];
        hidden = st2[0]; cell = st2[1];
    } else {
        x        = (const float*)d_in[0];
        ip       = (const int*)  d_in[1];
        port     = (const int*)  d_in[2];
        hidden   = (const float*)d_in[3];
        cell     = (const float*)d_in[4];
        ip_emb   = (const float*)d_in[5];
        port_emb = (const float*)d_in[6];
        Wih0     = (const float*)d_in[7];
        Whh0     = (const float*)d_in[8];
        bih0     = (const float*)d_in[9];
        bhh0     = (const float*)d_in[10];
        Wih1     = (const float*)d_in[11];
        Whh1     = (const float*)d_in[12];
        bih1     = (const float*)d_in[13];
        bhh1     = (const float*)d_in[14];
    }
    float* out = (float*)d_out;
    int write_state = (out_size >= (int)(T_STEPS * H + 4 * H)) ? 1 : 0;

    cudaFuncSetAttribute(lstm_kernel,
                         cudaFuncAttributeMaxDynamicSharedMemorySize,
                         SMEM_BYTES);

    init_kernel<<<1, 1024>>>(hidden);
    g0_kernel<<<T_STEPS / 8, 256>>>(x, ip, port, ip_emb, port_emb,
                                    Wih0, bih0, bhh0);
    lstm_kernel<<<GRID, THREADS, SMEM_BYTES>>>(Whh0, Wih1, Whh1,
                                               bih1, bhh1, cell, out,
                                               write_state);
}

// round 10
// speedup vs baseline: 1.2218x; 1.2218x over previous
#include <cuda_runtime.h>
#include <cuda_fp16.h>
#include <math.h>

// ---------------------------------------------------------------------------
// 2-layer LSTM, H=1024, T=4096 sequential steps. Persistent kernel, 146 CTAs.
//   A (0..51):   layer-0. W_hh0 fully in REGISTERS. G0 prefetch in regs.
//   B (52..145): layer-1. W_ih1 in SMEM (consumed pre-poll), W_hh1 in
//                REGISTERS (post-poll phase is pure reg HFMA2).
// ROUND-9: all-warps polling, lane-direct h loads (no smem staging, one
//   syncthreads/step), parity-double-buffered gate exchange, reg-resident
//   cell state + biases. Monotonic h history + banked release counters.
// ---------------------------------------------------------------------------

#define H        1024
#define T_STEPS  4096
#define GATES    4096
#define NA       52          // layer-0 CTAs
#define NUA      20          // units per A CTA (last ragged: 4)
#define NB       94          // layer-1 CTAs
#define NUB      11          // units per B CTA (last ragged: 1)
#define GRID     (NA + NB)   // 146
#define THREADS  512
#define BASE_OUT ((size_t)T_STEPS * H)
#define NBANKS   8

#define A_NROWS  (NUA * 4)   // 80
#define B_NROWS  (NUB * 4)   // 44

// ---- shared memory: B = [W_ih1 | sg parity]; A = [sg parity] ----
#define B_W_BYTES (B_NROWS * H * 2)            // 90112
#define B_SG_OFF  (B_W_BYTES)                  // 2 x 44 floats
#define SMEM_BYTES (B_SG_OFF + 2 * B_NROWS * 4 + 64)

// ---- device-global scratch ----
__device__ float          g_G0[(size_t)T_STEPS * GATES];        // 64 MB
__device__ unsigned short g_Hh0[(size_t)(T_STEPS + 1) * H];     // h0 history fp16
__device__ unsigned short g_Hh1[(size_t)(T_STEPS + 1) * H];     // h1 history fp16
__device__ unsigned       g_cntA_b[NBANKS * 64];
__device__ unsigned       g_cntB_b[NBANKS * 64];

__device__ __forceinline__ unsigned ld_acquire(const unsigned* p) {
    unsigned v;
    asm volatile("ld.acquire.gpu.global.u32 %0, [%1];"
                 : "=r"(v) : "l"(p) : "memory");
    return v;
}
__device__ __forceinline__ void red_release_add1(unsigned* p) {
    asm volatile("red.release.gpu.global.add.u32 [%0], %1;"
                 :: "l"(p), "r"(1u) : "memory");
}
__device__ __forceinline__ void stcg_u16(unsigned short* p, unsigned short v) {
    asm volatile("st.global.cg.u16 [%0], %1;" :: "l"(p), "h"(v));
}
__device__ __forceinline__ uint4 ldcg_u128(const uint4* p) {
    uint4 v;
    asm volatile("ld.global.cg.v4.u32 {%0,%1,%2,%3}, [%4];"
                 : "=r"(v.x), "=r"(v.y), "=r"(v.z), "=r"(v.w) : "l"(p));
    return v;
}

// full-warp poll: sum of 8 banks >= target
__device__ __forceinline__ void wait_banks(const unsigned* banks,
                                           unsigned target) {
    const int lane = threadIdx.x & 31;
    for (;;) {
        unsigned v = (lane < NBANKS) ? ld_acquire(&banks[lane << 6]) : 0u;
        v += __shfl_xor_sync(0xffffffffu, v, 1);
        v += __shfl_xor_sync(0xffffffffu, v, 2);
        v += __shfl_xor_sync(0xffffffffu, v, 4);
        v  = __shfl_sync(0xffffffffu, v, 0);
        if (v >= target) return;
    }
}

__device__ __forceinline__ void mac_granule4(const uint4& wq, const uint4& hq,
                                             __half2* acc) {
    acc[0] = __hfma2(*(const __half2*)&wq.x, *(const __half2*)&hq.x, acc[0]);
    acc[1] = __hfma2(*(const __half2*)&wq.y, *(const __half2*)&hq.y, acc[1]);
    acc[2] = __hfma2(*(const __half2*)&wq.z, *(const __half2*)&hq.z, acc[2]);
    acc[3] = __hfma2(*(const __half2*)&wq.w, *(const __half2*)&hq.w, acc[3]);
}
__device__ __forceinline__ float acc4_reduce(__half2* acc) {
    acc[0] = __hadd2(acc[0], acc[2]);
    acc[1] = __hadd2(acc[1], acc[3]);
    acc[0] = __hadd2(acc[0], acc[1]);
    float2 f = __half22float2(acc[0]);
    return f.x + f.y;
}
__device__ __forceinline__ float acc8_reduce(__half2* acc) {
    acc[0] = __hadd2(acc[0], acc[4]);
    acc[1] = __hadd2(acc[1], acc[5]);
    acc[2] = __hadd2(acc[2], acc[6]);
    acc[3] = __hadd2(acc[3], acc[7]);
    acc[0] = __hadd2(acc[0], acc[2]);
    acc[1] = __hadd2(acc[1], acc[3]);
    acc[0] = __hadd2(acc[0], acc[1]);
    float2 f = __half22float2(acc[0]);
    return f.x + f.y;
}

__device__ __forceinline__ float fsig(float x) {
    return __fdividef(1.f, 1.f + __expf(-x));
}
__device__ __forceinline__ float ftanh(float x) {
    return 1.f - __fdividef(2.f, __expf(2.f * x) + 1.f);
}
__device__ __forceinline__ unsigned pack_h2(float a, float b) {
    __half2 h = __halves2half2(__float2half_rn(a), __float2half_rn(b));
    return *(unsigned*)&h;
}

// ---------------------------------------------------------------------------
__global__ void init_kernel(const float* __restrict__ hidden) {
    int u = threadIdx.x;
    if (u < H) {
        g_Hh0[u] = __half_as_ushort(__float2half_rn(hidden[u]));
        g_Hh1[u] = __half_as_ushort(__float2half_rn(hidden[H + u]));
    }
    if (u < NBANKS * 64) { g_cntA_b[u] = 0u; g_cntB_b[u] = 0u; }
}

// ---------------------------------------------------------------------------
__global__ void g0_kernel(const float* __restrict__ x,
                          const int*   __restrict__ ip,
                          const int*   __restrict__ port,
                          const float* __restrict__ ip_emb,
                          const float* __restrict__ port_emb,
                          const float* __restrict__ Wih0,
                          const float* __restrict__ bih0,
                          const float* __restrict__ bhh0) {
    __shared__ float sxin[8][33];
    const int t0  = blockIdx.x * 8;
    const int tid = threadIdx.x;

    for (int idx = tid; idx < 8 * 33; idx += 256) {
        int tt = idx / 33, k = idx - tt * 33;
        int t = t0 + tt;
        float v;
        if (k < 17)      v = x[t * 17 + k];
        else if (k < 25) v = ip_emb[ip[t * 8 + (k - 17)]];
        else {
            int s = (k - 25) >> 2, e = (k - 25) & 3;
            v = port_emb[port[t * 2 + s] * 4 + e];
        }
        sxin[tt][k] = v;
    }
    __syncthreads();

    for (int j = tid; j < GATES; j += 256) {
        float w[33];
#pragma unroll
        for (int k = 0; k < 33; ++k) w[k] = __ldg(&Wih0[j * 33 + k]);
        float bias = __ldg(&bih0[j]) + __ldg(&bhh0[j]);
#pragma unroll
        for (int tt = 0; tt < 8; ++tt) {
            float acc = bias;
#pragma unroll
            for (int k = 0; k < 33; ++k) acc = fmaf(w[k], sxin[tt][k], acc);
            g_G0[(size_t)(t0 + tt) * GATES + j] = acc;
        }
    }
}

// ---------------------------------------------------------------------------
__global__ __launch_bounds__(THREADS, 1)
void lstm_kernel(const float* __restrict__ Whh0,
                 const float* __restrict__ Wih1,
                 const float* __restrict__ Whh1,
                 const float* __restrict__ bih1,
                 const float* __restrict__ bhh1,
                 const float* __restrict__ cell,
                 float* __restrict__ out,
                 int write_state) {
    extern __shared__ char smem[];
    const int tid  = threadIdx.x;
    const int lane = tid & 31;
    const int warp = tid >> 5;
    const int cta  = blockIdx.x;

    if (cta < NA) {
        // ================ layer 0 : everything in registers ================
        const int u0 = cta * NUA;
        const int nu = min(NUA, H - u0);
        const int nrows = 4 * nu;
        float* sg = (float*)smem;              // [2][A_NROWS]

        int grow_i[5];
        uint4 w[5][4];
#pragma unroll
        for (int i = 0; i < 5; ++i) {
            int r = warp + 16 * i;
            grow_i[i] = 0;
#pragma unroll
            for (int g = 0; g < 4; ++g) w[i][g] = make_uint4(0u, 0u, 0u, 0u);
            if (r < nrows) {
                int grow = (r & 3) * H + u0 + (r >> 2);
                grow_i[i] = grow;
                const float* src = Whh0 + (size_t)grow * H;
#pragma unroll
                for (int g = 0; g < 4; ++g) {
                    int base = (g * 32 + lane) * 8;
                    float4 f0 = *(const float4*)(src + base);
                    float4 f1 = *(const float4*)(src + base + 4);
                    w[i][g] = make_uint4(pack_h2(f0.x, f0.y), pack_h2(f0.z, f0.w),
                                         pack_h2(f1.x, f1.y), pack_h2(f1.z, f1.w));
                }
            }
        }
        float creg = (warp == 0 && lane < nu) ? cell[u0 + lane] : 0.f;
        __syncthreads();

        for (int t = 0; t < T_STEPS; ++t) {
            // G0 prefetch into regs — in flight during the poll
            float g0v[5];
#pragma unroll
            for (int i = 0; i < 5; ++i) {
                int r = warp + 16 * i;
                g0v[i] = (r < nrows)
                       ? __ldg(&g_G0[(size_t)t * GATES + grow_i[i]]) : 0.f;
            }
            wait_banks(g_cntA_b, (unsigned)(NA * t));     // all warps

            const uint4* hsrc = (const uint4*)(g_Hh0 + (size_t)t * H);
            uint4 hq[4];
#pragma unroll
            for (int g = 0; g < 4; ++g) hq[g] = ldcg_u128(&hsrc[g * 32 + lane]);

            float* sgp = sg + (t & 1) * A_NROWS;
#pragma unroll
            for (int i = 0; i < 5; ++i) {
                int r = warp + 16 * i;
                if (r < nrows) {
                    __half2 acc[4];
#pragma unroll
                    for (int a = 0; a < 4; ++a) acc[a] = __float2half2_rn(0.f);
#pragma unroll
                    for (int g = 0; g < 4; ++g) mac_granule4(w[i][g], hq[g], acc);
                    float s = acc4_reduce(acc);
#pragma unroll
                    for (int o = 16; o > 0; o >>= 1)
                        s += __shfl_xor_sync(0xffffffffu, s, o);
                    if (lane == 0) sgp[r] = s + g0v[i];
                }
            }
            __syncthreads();

            if (warp == 0) {
                if (lane < nu) {
                    float ii = fsig(sgp[lane * 4 + 0]);
                    float ff = fsig(sgp[lane * 4 + 1]);
                    float gg = ftanh(sgp[lane * 4 + 2]);
                    float oo = fsig(sgp[lane * 4 + 3]);
                    float c  = ff * creg + ii * gg;
                    creg = c;
                    float h  = oo * ftanh(c);
                    stcg_u16(&g_Hh0[(size_t)(t + 1) * H + u0 + lane],
                             __half_as_ushort(__float2half_rn(h)));
                    if (t == T_STEPS - 1 && write_state) {
                        out[BASE_OUT + u0 + lane]         = h;   // hf layer 0
                        out[BASE_OUT + 2 * H + u0 + lane] = c;   // cf layer 0
                    }
                }
                __syncwarp();
                if (lane == 0)
                    red_release_add1(&g_cntA_b[(cta & (NBANKS - 1)) << 6]);
            }
        }
    } else {
        // ====== layer 1 : W_ih1 in SMEM (pre-poll), W_hh1 in registers ======
        const int b  = cta - NA;
        const int u0 = b * NUB;
        const int nu = min(NUB, H - u0);
        const int nrows = 4 * nu;
        __half* sw = (__half*)smem;            // W_ih1: nrows x 1024 halves
        float*  sg = (float*)(smem + B_SG_OFF);// [2][B_NROWS]

        for (int idx = tid; idx < nrows * H; idx += THREADS) {
            int r = idx >> 10, k = idx & (H - 1);
            int grow = (r & 3) * H + u0 + (r >> 2);
            sw[idx] = __float2half_rn(Wih1[(size_t)grow * H + k]);
        }
        uint4 w2[3][4];
        float bs[3];
#pragma unroll
        for (int i = 0; i < 3; ++i) {
            int r = warp + 16 * i;
            bs[i] = 0.f;
#pragma unroll
            for (int g = 0; g < 4; ++g) w2[i][g] = make_uint4(0u, 0u, 0u, 0u);
            if (r < nrows) {
                int grow = (r & 3) * H + u0 + (r >> 2);
                bs[i] = __ldg(&bih1[grow]) + __ldg(&bhh1[grow]);
                const float* src = Whh1 + (size_t)grow * H;
#pragma unroll
                for (int g = 0; g < 4; ++g) {
                    int base = (g * 32 + lane) * 8;
                    float4 f0 = *(const float4*)(src + base);
                    float4 f1 = *(const float4*)(src + base + 4);
                    w2[i][g] = make_uint4(pack_h2(f0.x, f0.y), pack_h2(f0.z, f0.w),
                                          pack_h2(f1.x, f1.y), pack_h2(f1.z, f1.w));
                }
            }
        }
        float creg = (warp == 0 && lane < nu) ? cell[H + u0 + lane] : 0.f;
        __syncthreads();

        for (int t = 0; t < T_STEPS; ++t) {
            // ---- phase 1: W_ih1 (SMEM) @ h0(t) — cntA usually far ahead ----
            wait_banks(g_cntA_b, (unsigned)(NA * (t + 1)));
            const uint4* h0src = (const uint4*)(g_Hh0 + (size_t)(t + 1) * H);
            uint4 hq[4];
#pragma unroll
            for (int g = 0; g < 4; ++g) hq[g] = ldcg_u128(&h0src[g * 32 + lane]);

            __half2 acc[3][8];
#pragma unroll
            for (int i = 0; i < 3; ++i)
#pragma unroll
                for (int q = 0; q < 8; ++q) acc[i][q] = __float2half2_rn(0.f);

#pragma unroll
            for (int i = 0; i < 3; ++i) {
                int r = warp + 16 * i;
                if (r < nrows) {
                    const uint4* wrow = (const uint4*)(sw + (size_t)r * H);
#pragma unroll
                    for (int g = 0; g < 4; ++g)
                        mac_granule4(wrow[g * 32 + lane], hq[g], acc[i]);
                }
            }

            // ---- phase 2: W_hh1 (REGS) @ h1(t-1) ----
            wait_banks(g_cntB_b, (unsigned)(NB * t));
            const uint4* h1src = (const uint4*)(g_Hh1 + (size_t)t * H);
#pragma unroll
            for (int g = 0; g < 4; ++g) hq[g] = ldcg_u128(&h1src[g * 32 + lane]);

            float* sgp = sg + (t & 1) * B_NROWS;
#pragma unroll
            for (int i = 0; i < 3; ++i) {
                int r = warp + 16 * i;
                if (r < nrows) {
#pragma unroll
                    for (int g = 0; g < 4; ++g)
                        mac_granule4(w2[i][g], hq[g], acc[i] + 4);
                    float s = acc8_reduce(acc[i]);
#pragma unroll
                    for (int o = 16; o > 0; o >>= 1)
                        s += __shfl_xor_sync(0xffffffffu, s, o);
                    if (lane == 0) sgp[r] = s + bs[i];
                }
            }
            __syncthreads();

            if (warp == 0) {
                if (lane < nu) {
                    float ii = fsig(sgp[lane * 4 + 0]);
                    float ff = fsig(sgp[lane * 4 + 1]);
                    float gg = ftanh(sgp[lane * 4 + 2]);
                    float oo = fsig(sgp[lane * 4 + 3]);
                    float c  = ff * creg + ii * gg;
                    creg = c;
                    float h  = oo * ftanh(c);
                    stcg_u16(&g_Hh1[(size_t)(t + 1) * H + u0 + lane],
                             __half_as_ushort(__float2half_rn(h)));
                    out[(size_t)t * H + u0 + lane] = fmaxf(h, 0.f);
                    if (t == T_STEPS - 1 && write_state) {
                        out[BASE_OUT + H + u0 + lane]     = h;   // hf layer 1
                        out[BASE_OUT + 3 * H + u0 + lane] = c;   // cf layer 1
                    }
                }
                __syncwarp();
                if (lane == 0)
                    red_release_add1(&g_cntB_b[(cta & (NBANKS - 1)) << 6]);
            }
        }
    }
}

// ---------------------------------------------------------------------------
extern "C" void kernel_launch(void* const* d_in, const int* in_sizes, int n_in,
                              void* d_out, int out_size) {
    const float *x = 0, *hidden = 0, *cell = 0, *ip_emb = 0, *port_emb = 0;
    const float *Wih0 = 0, *Whh0 = 0, *bih0 = 0, *bhh0 = 0;
    const float *Wih1 = 0, *Whh1 = 0, *bih1 = 0, *bhh1 = 0;
    const int *ip = 0, *port = 0;

    const float* big[3]  = {0, 0, 0};    int nbig  = 0;
    const float* bias[4] = {0, 0, 0, 0}; int nbias = 0;
    const float* st2[2]  = {0, 0};       int nst2  = 0;

    for (int i = 0; i < n_in; ++i) {
        switch (in_sizes[i]) {
            case 69632:   x        = (const float*)d_in[i]; break;
            case 32768:   ip       = (const int*)  d_in[i]; break;
            case 8192:    port     = (const int*)  d_in[i]; break;
            case 256:     ip_emb   = (const float*)d_in[i]; break;
            case 280000:  port_emb = (const float*)d_in[i]; break;
            case 135168:  Wih0     = (const float*)d_in[i]; break;
            case 4194304: if (nbig  < 3) big[nbig++]   = (const float*)d_in[i]; break;
            case 4096:    if (nbias < 4) bias[nbias++] = (const float*)d_in[i]; break;
            case 2048:    if (nst2  < 2) st2[nst2++]   = (const float*)d_in[i]; break;
            default: break;
        }
    }
    if (nbig == 3 && nbias == 4 && nst2 == 2 && x && ip && port &&
        ip_emb && port_emb && Wih0) {
        Whh0 = big[0]; Wih1 = big[1]; Whh1 = big[2];
        bih0 = bias[0]; bhh0 = bias[1]; bih1 = bias[2]; bhh1 = bias[3];
        hidden = st2[0]; cell = st2[1];
    } else {
        x        = (const float*)d_in[0];
        ip       = (const int*)  d_in[1];
        port     = (const int*)  d_in[2];
        hidden   = (const float*)d_in[3];
        cell     = (const float*)d_in[4];
        ip_emb   = (const float*)d_in[5];
        port_emb = (const float*)d_in[6];
        Wih0     = (const float*)d_in[7];
        Whh0     = (const float*)d_in[8];
        bih0     = (const float*)d_in[9];
        bhh0     = (const float*)d_in[10];
        Wih1     = (const float*)d_in[11];
        Whh1     = (const float*)d_in[12];
        bih1     = (const float*)d_in[13];
        bhh1     = (const float*)d_in[14];
    }
    float* out = (float*)d_out;
    int write_state = (out_size >= (int)(T_STEPS * H + 4 * H)) ? 1 : 0;

    cudaFuncSetAttribute(lstm_kernel,
                         cudaFuncAttributeMaxDynamicSharedMemorySize,
                         SMEM_BYTES);

    init_kernel<<<1, 1024>>>(hidden);
    g0_kernel<<<T_STEPS / 8, 256>>>(x, ip, port, ip_emb, port_emb,
                                    Wih0, bih0, bhh0);
    lstm_kernel<<<GRID, THREADS, SMEM_BYTES>>>(Whh0, Wih1, Whh1,
                                               bih1, bhh1, cell, out,
                                               write_state);
}